// round 4
// baseline (speedup 1.0000x reference)
#include <cuda_runtime.h>
#include <cstdint>

// SVD predict: cp.async gather -> smem tile -> TMA bulk store.
//
// Inputs (metadata order):
//   d_in[0] user_item  int32  [131072, 2]
//   d_in[1] pu         f32    [1000000, 64]
//   d_in[2] qi         f32    [500000, 64]
//   d_in[3] bu         f32    [1000000]
//   d_in[4] bi         f32    [500000]
//   d_in[5] global_mean f32   [1]
// Output: float32 [131072 predict] ++ [131072 x 128 features]

#define BATCH        131072
#define ROWS_PER_CTA 64
#define THREADS      256
#define ROW_FLOATS   128          // [p(64) | q(64)]
#define TILE_BYTES   (ROWS_PER_CTA * ROW_FLOATS * 4)   // 32 KB

__device__ __forceinline__ uint32_t smem_u32(const void* p) {
    uint32_t a;
    asm("{ .reg .u64 t; cvta.to.shared.u64 t, %1; cvt.u32.u64 %0, t; }"
        : "=r"(a) : "l"(p));
    return a;
}

__global__ __launch_bounds__(THREADS)
void svd_predict_kernel(const int2* __restrict__ ui,
                        const float4* __restrict__ pu4,   // [N_USERS][16]
                        const float4* __restrict__ qi4,   // [N_ITEMS][16]
                        const float* __restrict__ bu,
                        const float* __restrict__ bi,
                        const float* __restrict__ gm,
                        float* __restrict__ out_pred,
                        float* __restrict__ out_feat)     // [BATCH][128]
{
    __shared__ __align__(128) float tile[ROWS_PER_CTA * ROW_FLOATS];

    const int t  = threadIdx.x;
    const int r0 = blockIdx.x * ROWS_PER_CTA;
    const uint32_t s_base = smem_u32(tile);

    // ---- Phase 1: 2048 x 16B cp.async gathers (8 per thread, no reg dest) ----
    // j = t + k*256; row = j>>5 (one row per warp-iteration), c = j&31.
    // c in [0,16): p chunk c;  c in [16,32): q chunk c-16.
    #pragma unroll
    for (int k = 0; k < 8; k++) {
        const int j   = t + k * THREADS;
        const int row = j >> 5;
        const int c   = j & 31;
        const int2 ids = __ldg(&ui[r0 + row]);
        const float4* src = (c < 16)
            ? pu4 + (size_t)ids.x * 16 + c
            : qi4 + (size_t)ids.y * 16 + (c - 16);
        const uint32_t dst = s_base + (uint32_t)(row * ROW_FLOATS + c * 4) * 4u;
        asm volatile("cp.async.cg.shared.global [%0], [%1], 16;\n"
                     :: "r"(dst), "l"(src));
    }
    asm volatile("cp.async.commit_group;\n"
                 "cp.async.wait_group 0;\n" ::: "memory");
    __syncthreads();

    // ---- Phase 2: dot products + predictions ----
    const int warp = t >> 5;
    const int lane = t & 31;
    const float base = __ldg(gm);

    #pragma unroll
    for (int k = 0; k < 8; k++) {
        const int row = warp * 8 + k;
        const float2* r2 = reinterpret_cast<const float2*>(tile + row * ROW_FLOATS);
        const float2 p = r2[lane];
        const float2 q = r2[lane + 32];
        float d = p.x * q.x + p.y * q.y;
        #pragma unroll
        for (int off = 16; off; off >>= 1)
            d += __shfl_xor_sync(0xFFFFFFFFu, d, off);
        if (lane == 0) {
            const int2 ids = __ldg(&ui[r0 + row]);
            float pr = base + __ldg(&bu[ids.x]) + __ldg(&bi[ids.y]) + d;
            out_pred[r0 + row] = fminf(fmaxf(pr, 1.0f), 5.0f);
        }
    }
    __syncthreads();

    // ---- Phase 3: one 32KB TMA bulk store, smem -> contiguous feature rows ----
    if (t == 0) {
        float* dst = out_feat + (size_t)r0 * ROW_FLOATS;
        asm volatile("cp.async.bulk.global.shared::cta.bulk_group [%0], [%1], %2;\n"
                     :: "l"(dst), "r"(s_base), "r"((uint32_t)TILE_BYTES)
                     : "memory");
        asm volatile("cp.async.bulk.commit_group;\n"
                     "cp.async.bulk.wait_group.read 0;\n" ::: "memory");
    }
}

extern "C" void kernel_launch(void* const* d_in, const int* in_sizes, int n_in,
                              void* d_out, int out_size)
{
    const int2*   ui  = (const int2*)  d_in[0];
    const float4* pu4 = (const float4*)d_in[1];
    const float4* qi4 = (const float4*)d_in[2];
    const float*  bu  = (const float*) d_in[3];
    const float*  bi  = (const float*) d_in[4];
    const float*  gm  = (const float*) d_in[5];

    float* out_pred = (float*)d_out;               // [BATCH]
    float* out_feat = out_pred + BATCH;            // [BATCH][128]

    const int blocks = BATCH / ROWS_PER_CTA;       // 2048
    svd_predict_kernel<<<blocks, THREADS>>>(ui, pu4, qi4, bu, bi, gm,
                                            out_pred, out_feat);
}

// round 5
// speedup vs baseline: 1.1764x; 1.1764x over previous
#include <cuda_runtime.h>
#include <cstdint>

// SVD predict: warp-autonomous cp.async gather -> smem -> per-warp bulk store.
// No __syncthreads anywhere; each warp owns 8 rows end-to-end.
//
// Inputs (metadata order):
//   d_in[0] user_item  int32  [131072, 2]
//   d_in[1] pu         f32    [1000000, 64]
//   d_in[2] qi         f32    [500000, 64]
//   d_in[3] bu         f32    [1000000]
//   d_in[4] bi         f32    [500000]
//   d_in[5] global_mean f32   [1]
// Output: float32 [131072 predict] ++ [131072 x 128 features]

#define BATCH         131072
#define THREADS       128
#define WARPS_PER_CTA 4
#define ROWS_PER_WARP 8
#define ROWS_PER_CTA  (WARPS_PER_CTA * ROWS_PER_WARP)   // 32
#define ROW_FLOATS    128                               // [p(64) | q(64)]

__device__ __forceinline__ uint32_t smem_u32(const void* p) {
    uint32_t a;
    asm("{ .reg .u64 t; cvta.to.shared.u64 t, %1; cvt.u32.u64 %0, t; }"
        : "=r"(a) : "l"(p));
    return a;
}

__global__ __launch_bounds__(THREADS)
void svd_predict_kernel(const int2* __restrict__ ui,
                        const float4* __restrict__ pu4,   // [N_USERS][16]
                        const float4* __restrict__ qi4,   // [N_ITEMS][16]
                        const float* __restrict__ bu,
                        const float* __restrict__ bi,
                        const float* __restrict__ gm,
                        float* __restrict__ out_pred,
                        float* __restrict__ out_feat)     // [BATCH][128]
{
    __shared__ __align__(128) float tile[ROWS_PER_CTA * ROW_FLOATS];  // 16 KB

    const int t    = threadIdx.x;
    const int warp = t >> 5;
    const int lane = t & 31;

    const int wrow0 = blockIdx.x * ROWS_PER_CTA + warp * ROWS_PER_WARP;
    float* const wtile = tile + warp * ROWS_PER_WARP * ROW_FLOATS;

    // Per-row ids, fetched by lanes 0..7 and broadcast via shuffle.
    int2 myids = make_int2(0, 0);
    if (lane < ROWS_PER_WARP) myids = __ldg(&ui[wrow0 + lane]);

    // ---- Gather: 8 rows x 32 chunks of 16B via cp.async (no dest regs) ----
    // lane c: c<16 -> p chunk c ; c>=16 -> q chunk c-16.
    #pragma unroll
    for (int k = 0; k < ROWS_PER_WARP; k++) {
        const int uid = __shfl_sync(0xFFFFFFFFu, myids.x, k);
        const int iid = __shfl_sync(0xFFFFFFFFu, myids.y, k);
        const float4* src = (lane < 16)
            ? pu4 + (size_t)uid * 16 + lane
            : qi4 + (size_t)iid * 16 + (lane - 16);
        const uint32_t dst = smem_u32(wtile + k * ROW_FLOATS + lane * 4);
        asm volatile("cp.async.cg.shared.global [%0], [%1], 16;\n"
                     :: "r"(dst), "l"(src));
        if (k == 3)
            asm volatile("cp.async.commit_group;\n" ::: "memory");
    }
    asm volatile("cp.async.commit_group;\n" ::: "memory");

    // ---- Dots: first half while second half is still in flight ----
    float myd = 0.0f;   // lane k<8 ends up holding dot of row k

    asm volatile("cp.async.wait_group 1;\n" ::: "memory");
    __syncwarp();
    #pragma unroll
    for (int k = 0; k < 4; k++) {
        const float2* r2 = reinterpret_cast<const float2*>(wtile + k * ROW_FLOATS);
        const float2 p = r2[lane];
        const float2 q = r2[lane + 32];
        float d = p.x * q.x + p.y * q.y;
        #pragma unroll
        for (int off = 16; off; off >>= 1)
            d += __shfl_xor_sync(0xFFFFFFFFu, d, off);
        if (lane == k) myd = d;
    }

    asm volatile("cp.async.wait_group 0;\n" ::: "memory");
    __syncwarp();
    #pragma unroll
    for (int k = 4; k < ROWS_PER_WARP; k++) {
        const float2* r2 = reinterpret_cast<const float2*>(wtile + k * ROW_FLOATS);
        const float2 p = r2[lane];
        const float2 q = r2[lane + 32];
        float d = p.x * q.x + p.y * q.y;
        #pragma unroll
        for (int off = 16; off; off >>= 1)
            d += __shfl_xor_sync(0xFFFFFFFFu, d, off);
        if (lane == k) myd = d;
    }

    // ---- Predictions: lanes 0..7 gather biases in parallel ----
    if (lane < ROWS_PER_WARP) {
        float pr = __ldg(gm) + __ldg(&bu[myids.x]) + __ldg(&bi[myids.y]) + myd;
        out_pred[wrow0 + lane] = fminf(fmaxf(pr, 1.0f), 5.0f);
    }

    // ---- Feature store: one 4KB bulk copy per warp (contiguous) ----
    asm volatile("fence.proxy.async.shared::cta;\n" ::: "memory");
    __syncwarp();
    if (lane == 0) {
        float* dst = out_feat + (size_t)wrow0 * ROW_FLOATS;
        asm volatile("cp.async.bulk.global.shared::cta.bulk_group [%0], [%1], %2;\n"
                     :: "l"(dst), "r"(smem_u32(wtile)),
                        "r"((uint32_t)(ROWS_PER_WARP * ROW_FLOATS * 4))
                     : "memory");
        asm volatile("cp.async.bulk.commit_group;\n"
                     "cp.async.bulk.wait_group.read 0;\n" ::: "memory");
    }
}

extern "C" void kernel_launch(void* const* d_in, const int* in_sizes, int n_in,
                              void* d_out, int out_size)
{
    const int2*   ui  = (const int2*)  d_in[0];
    const float4* pu4 = (const float4*)d_in[1];
    const float4* qi4 = (const float4*)d_in[2];
    const float*  bu  = (const float*) d_in[3];
    const float*  bi  = (const float*) d_in[4];
    const float*  gm  = (const float*) d_in[5];

    float* out_pred = (float*)d_out;               // [BATCH]
    float* out_feat = out_pred + BATCH;            // [BATCH][128]

    const int blocks = BATCH / ROWS_PER_CTA;       // 4096
    svd_predict_kernel<<<blocks, THREADS>>>(ui, pu4, qi4, bu, bi, gm,
                                            out_pred, out_feat);
}